// round 12
// baseline (speedup 1.0000x reference)
#include <cuda_runtime.h>

#define TT 256
#define MM 16
#define HH 256
#define II 128
#define NROW (MM*HH)          // 4096
#define NB 128                // 128 CTAs; 16 warps each; warp owns 2 rows of its module
#define NTHR 512
#define BIN_THR 256
#define SLOTCAP 200           // int16 weight slots; 1 slot = 2 rows x 256 s16 = 1KB
#define DSMEM_BYTES (SLOTCAP*1024)

#define DT_ 0.042f
#define GAMMA_ 2.7f
#define EPS_ 4.7f

// ---- persistent scratch (no cudaMalloc allowed) ----
__device__ float    g_B[TT*NROW];     // W_in@u + bias, 4 MB
__device__ float    g_hy[2][NROW];    // double-buffered published hy
__device__ unsigned g_bar;

// ============================================================
// Precompute B[t, m*H+h]
// ============================================================
__global__ void bin_kernel(const float* __restrict__ x,
                           const float* __restrict__ input_mask,
                           const float* __restrict__ W_in,
                           const float* __restrict__ bias) {
    __shared__ float4 xs[II/4];
    int t = blockIdx.x, m = blockIdx.y, h = threadIdx.x;
    if (h < II/4) xs[h] = ((const float4*)(x + (size_t)t*II))[h];
    __syncthreads();
    const float4* w4 = (const float4*)(W_in + ((size_t)m*HH + h)*II);
    float s = 0.f;
#pragma unroll
    for (int k = 0; k < II/4; ++k) {
        float4 a = w4[k], b = xs[k];
        s += a.x*b.x + a.y*b.y + a.z*b.z + a.w*b.w;
    }
    g_B[((size_t)t*MM + m)*HH + h] = input_mask[m]*s + bias[m*HH + h];
}

__device__ __forceinline__ float dotf4(float4 a, float4 b) {
    return a.x*b.x + a.y*b.y + a.z*b.z + a.w*b.w;
}
__device__ __forceinline__ float s16lo(unsigned v){ return (float)((short)(v & 0xffffu)); }
__device__ __forceinline__ float s16hi(unsigned v){ return (float)((short)(v >> 16)); }

// 8 quantized weights (packed s16) vs two hy float4s
__device__ __forceinline__ float dot8q(uint4 q, float4 b0, float4 b1) {
    float s;
    s  = s16lo(q.x)*b0.x + s16hi(q.x)*b0.y;
    s += s16lo(q.y)*b0.z + s16hi(q.y)*b0.w;
    s += s16lo(q.z)*b1.x + s16hi(q.z)*b1.y;
    s += s16lo(q.w)*b1.z + s16hi(q.w)*b1.w;
    return s;
}

__device__ __forceinline__ unsigned pack2(float x, float y, float inv) {
    int a = __float2int_rn(x*inv), b = __float2int_rn(y*inv);
    return ((unsigned)a & 0xffffu) | ((unsigned)b << 16);
}

// Quantize one slot (2 rows x 256 fp32 -> s16) into smem, warp-collective.
// Row data is read in the SAME lane layout used by the dot (f4 at lane and
// lane+32), so the packed uint4 per lane is already "permuted" correctly.
__device__ __forceinline__ void quant_slot(uint4* wq, float* scale_sh, int slot,
                                           const float4* src0, const float4* src1,
                                           int lane) {
    float4 a0 = src0[lane], a1 = src0[lane+32];
    float4 c0 = src1[lane], c1 = src1[lane+32];
    float m = fmaxf(fabsf(a0.x), fabsf(a0.y));
    m = fmaxf(m, fmaxf(fabsf(a0.z), fabsf(a0.w)));
    m = fmaxf(m, fmaxf(fabsf(a1.x), fabsf(a1.y)));
    m = fmaxf(m, fmaxf(fabsf(a1.z), fabsf(a1.w)));
    m = fmaxf(m, fmaxf(fabsf(c0.x), fabsf(c0.y)));
    m = fmaxf(m, fmaxf(fabsf(c0.z), fabsf(c0.w)));
    m = fmaxf(m, fmaxf(fabsf(c1.x), fabsf(c1.y)));
    m = fmaxf(m, fmaxf(fabsf(c1.z), fabsf(c1.w)));
#pragma unroll
    for (int off = 16; off; off >>= 1)
        m = fmaxf(m, __shfl_xor_sync(0xffffffffu, m, off));
    float inv = (m > 0.f) ? 32766.f/m : 0.f;
    uint4 qa = { pack2(a0.x,a0.y,inv), pack2(a0.z,a0.w,inv),
                 pack2(a1.x,a1.y,inv), pack2(a1.z,a1.w,inv) };
    uint4 qb = { pack2(c0.x,c0.y,inv), pack2(c0.z,c0.w,inv),
                 pack2(c1.x,c1.y,inv), pack2(c1.z,c1.w,inv) };
    wq[slot*64 + lane]      = qa;
    wq[slot*64 + 32 + lane] = qb;
    if (lane == 0) scale_sh[slot] = (m > 0.f) ? m/32766.f : 0.f;
}

// ============================================================
// Persistent step kernel. Warp w = module i, rows h0=bid, h1=128+bid.
// ALL nonzero wm blocks + wrec live in SMEM as int16 (quantized at preload,
// per-slot scale). fp32-from-L2 fallback only if slots overflow (never
// in practice: E[slots]=144 << 200).
// ============================================================
__global__ void __launch_bounds__(NTHR, 1)
step_kernel(const float* __restrict__ wm,
            const float* __restrict__ conn,
            const float* __restrict__ wrec,
            float* __restrict__ out) {
    extern __shared__ uint4 wq[];        // [SLOTCAP][2][32] uint4 = 200 KB
    __shared__ float hy_sh[NROW];        // 16 KB snapshot
    __shared__ float scale_sh[SLOTCAP];
    __shared__ int   list_sh[MM][MM];
    __shared__ int   cnt_sh[MM];
    __shared__ float scal_sh[MM];

    int tid  = threadIdx.x;
    int lane = tid & 31;
    int i    = tid >> 5;                 // warp = module
    int h0   = blockIdx.x;
    int h1   = 128 + blockIdx.x;

    if (tid < MM) {
        int c = 0; float s = 0.f;
#pragma unroll
        for (int o = 0; o < MM; ++o) {
            float v = conn[tid*MM + o];
            s += v;
            if (v != 0.f) list_sh[tid][c++] = o;
        }
        cnt_sh[tid]  = c;
        scal_sh[tid] = 1.f / fmaxf(s, 1.f);
    }
    __syncthreads();

    const int   cnt  = cnt_sh[i];
    const float scal = scal_sh[i];
    const float* wmb0 = wm + (((size_t)i*MM)*HH + h0)*HH;
    const float* wmb1 = wm + (((size_t)i*MM)*HH + h1)*HH;

    // deterministic slot allocation: slots 0..15 = wrec per module;
    // wm pool from slot 16, module order, capped at SLOTCAP.
    int myoff = MM, myKC = 0;
    {
        int off = MM;
        for (int m2 = 0; m2 < MM; ++m2) {
            int rem  = SLOTCAP - off;
            int take = cnt_sh[m2];
            if (take > rem) take = rem > 0 ? rem : 0;
            if (m2 == i) { myoff = off; myKC = take; }
            off += take;
        }
    }

    // ---- one-time quantize+preload (warp-local writes, no sync needed) ----
    quant_slot(wq, scale_sh, i,
               (const float4*)(wrec + ((size_t)i*HH + h0)*HH),
               (const float4*)(wrec + ((size_t)i*HH + h1)*HH), lane);
    for (int k = 0; k < myKC; ++k) {
        int o = list_sh[i][k];
        quant_slot(wq, scale_sh, myoff + k,
                   (const float4*)(wmb0 + (size_t)o*HH*HH),
                   (const float4*)(wmb1 + (size_t)o*HH*HH), lane);
    }

    float hypA = 0.f, hzpA = 0.f, hypB = 0.f, hzpB = 0.f;
    float BvA = g_B[i*HH + h0];
    float BvB = g_B[i*HH + h1];

    float* state_out = out;                       // [T][M][2][H]
    float* fb_out    = out + (size_t)TT*MM*2*HH;  // [T][M][H]
    unsigned* barp = &g_bar;

    for (int t = 0; t < TT; ++t) {
        int p = t & 1;
        // cooperative snapshot of published hy (2 float4/thread)
        {
            const float4* src = (const float4*)g_hy[p];
            ((float4*)hy_sh)[tid]        = __ldcg(src + tid);
            ((float4*)hy_sh)[tid + NTHR] = __ldcg(src + tid + NTHR);
        }
        __syncthreads();

        const float4* hy4 = (const float4*)hy_sh;
        float fbA = 0.f, fbB = 0.f;

        // ---- cached int16 blocks (normal path: all of them) ----
        for (int k = 0; k < myKC; ++k) {
            int o = list_sh[i][k];
            int sl = myoff + k;
            float4 b0 = hy4[o*64 + lane], b1 = hy4[o*64 + 32 + lane];
            uint4 qa = wq[sl*64 + lane];
            uint4 qb = wq[sl*64 + 32 + lane];
            float scl = scale_sh[sl];
            fbA = fmaf(scl, dot8q(qa, b0, b1), fbA);
            fbB = fmaf(scl, dot8q(qb, b0, b1), fbB);
        }
        // ---- overflow blocks from L2, fp32 (statistically never runs) ----
        for (int k = myKC; k < cnt; ++k) {
            int o = list_sh[i][k];
            const float4* w0 = (const float4*)(wmb0 + (size_t)o*HH*HH);
            const float4* w1 = (const float4*)(wmb1 + (size_t)o*HH*HH);
            float4 b0 = hy4[o*64 + lane], b1 = hy4[o*64 + 32 + lane];
            fbA += dotf4(w0[lane], b0) + dotf4(w0[lane+32], b1);
            fbB += dotf4(w1[lane], b0) + dotf4(w1[lane+32], b1);
        }
        // ---- wrec (slot i) ----
        float recA, recB;
        {
            float4 b0 = hy4[i*64 + lane], b1 = hy4[i*64 + 32 + lane];
            uint4 qa = wq[i*64 + lane];
            uint4 qb = wq[i*64 + 32 + lane];
            float scl = scale_sh[i];
            recA = scl * dot8q(qa, b0, b1);
            recB = scl * dot8q(qb, b0, b1);
        }

#pragma unroll
        for (int off = 16; off; off >>= 1) {
            fbA  += __shfl_xor_sync(0xffffffffu, fbA,  off);
            fbB  += __shfl_xor_sync(0xffffffffu, fbB,  off);
            recA += __shfl_xor_sync(0xffffffffu, recA, off);
            recB += __shfl_xor_sync(0xffffffffu, recB, off);
        }
        fbA *= scal; fbB *= scal;
        float preA = fbA + recA + BvA;
        float preB = fbB + recB + BvB;
        float hznA = hzpA + DT_ * (tanhf(preA) - GAMMA_*hypA - EPS_*hzpA);
        float hynA = hypA + DT_ * hznA;
        float hznB = hzpB + DT_ * (tanhf(preB) - GAMMA_*hypB - EPS_*hzpB);
        float hynB = hypB + DT_ * hznB;
        hzpA = hznA; hypA = hynA; hzpB = hznB; hypB = hynB;

        size_t sb = ((size_t)(t*MM + i)*2)*HH;
        if (lane == 0) {
            state_out[sb + h0]      = hynA;
            state_out[sb + HH + h0] = hznA;
            fb_out[(size_t)(t*MM + i)*HH + h0] = fbA;
            __stcg(&g_hy[1-p][i*HH + h0], hynA);
        } else if (lane == 1) {
            state_out[sb + h1]      = hynB;
            state_out[sb + HH + h1] = hznB;
            fb_out[(size_t)(t*MM + i)*HH + h1] = fbB;
            __stcg(&g_hy[1-p][i*HH + h1], hynB);
        }

        if (t == TT-1) break;

        // prefetch next-step B while the barrier drains
        BvA = g_B[(size_t)(t+1)*NROW + i*HH + h0];
        BvB = g_B[(size_t)(t+1)*NROW + i*HH + h1];

        __syncthreads();                 // all rows of CTA published
        if (tid == 0) {
            asm volatile("red.release.gpu.global.add.u32 [%0], 1;"
                         :: "l"(barp) : "memory");
            unsigned target = (unsigned)NB * (unsigned)(t + 1);
            unsigned v;
            do {
                asm volatile("ld.acquire.gpu.global.u32 %0, [%1];"
                             : "=r"(v) : "l"(barp) : "memory");
            } while (v < target);
        }
        __syncthreads();
    }
}

extern "C" void kernel_launch(void* const* d_in, const int* in_sizes, int n_in,
                              void* d_out, int out_size) {
    const float* x     = (const float*)d_in[0];
    const float* wm    = (const float*)d_in[1];
    const float* conn  = (const float*)d_in[2];
    const float* mask  = (const float*)d_in[3];
    const float* W_in  = (const float*)d_in[4];
    const float* W_rec = (const float*)d_in[5];
    const float* bias  = (const float*)d_in[6];
    float* out = (float*)d_out;

    void *hy_ptr, *bar_ptr;
    cudaGetSymbolAddress(&hy_ptr,  g_hy);
    cudaGetSymbolAddress(&bar_ptr, g_bar);

    cudaMemsetAsync(hy_ptr, 0, sizeof(float)*NROW);
    cudaMemsetAsync(bar_ptr, 0, sizeof(unsigned));

    cudaFuncSetAttribute(step_kernel,
                         cudaFuncAttributeMaxDynamicSharedMemorySize, DSMEM_BYTES);

    bin_kernel<<<dim3(TT, MM), BIN_THR>>>(x, mask, W_in, bias);
    step_kernel<<<NB, NTHR, DSMEM_BYTES>>>(wm, conn, W_rec, out);
}

// round 13
// speedup vs baseline: 1.2978x; 1.2978x over previous
#include <cuda_runtime.h>
#include <cuda_fp16.h>

#define TT 256
#define MM 16
#define HH 256
#define II 128
#define NROW (MM*HH)          // 4096
#define NB 128                // 128 CTAs; 16 warps each; warp owns 2 rows of its module
#define NTHR 512
#define BIN_THR 256
#define SLOTCAP 200           // fp16 weight slots; 1 slot = 2 rows x 256 half = 1KB
#define DSMEM_BYTES (SLOTCAP*1024)

#define DT_ 0.042f
#define GAMMA_ 2.7f
#define EPS_ 4.7f

// ---- persistent scratch (no cudaMalloc allowed) ----
__device__ float    g_B[TT*NROW];     // W_in@u + bias, 4 MB
__device__ float    g_hy[2][NROW];    // double-buffered published hy
__device__ unsigned g_bar;

// ============================================================
// Precompute B[t, m*H+h]
// ============================================================
__global__ void bin_kernel(const float* __restrict__ x,
                           const float* __restrict__ input_mask,
                           const float* __restrict__ W_in,
                           const float* __restrict__ bias) {
    __shared__ float4 xs[II/4];
    int t = blockIdx.x, m = blockIdx.y, h = threadIdx.x;
    if (h < II/4) xs[h] = ((const float4*)(x + (size_t)t*II))[h];
    __syncthreads();
    const float4* w4 = (const float4*)(W_in + ((size_t)m*HH + h)*II);
    float s = 0.f;
#pragma unroll
    for (int k = 0; k < II/4; ++k) {
        float4 a = w4[k], b = xs[k];
        s += a.x*b.x + a.y*b.y + a.z*b.z + a.w*b.w;
    }
    g_B[((size_t)t*MM + m)*HH + h] = input_mask[m]*s + bias[m*HH + h];
}

__device__ __forceinline__ float dotf4(float4 a, float4 b) {
    return a.x*b.x + a.y*b.y + a.z*b.z + a.w*b.w;
}

// ---- packed f32x2 helpers (FFMA2 path; ptxas never emits from C++) ----
__device__ __forceinline__ unsigned long long pk2(float lo, float hi) {
    unsigned long long r;
    asm("mov.b64 %0, {%1, %2};" : "=l"(r) : "f"(lo), "f"(hi));
    return r;
}
__device__ __forceinline__ void fma2(unsigned long long& acc,
                                     unsigned long long a, unsigned long long b) {
    asm("fma.rn.f32x2 %0, %1, %2, %3;" : "=l"(acc) : "l"(a), "l"(b), "l"(acc));
}
__device__ __forceinline__ unsigned long long h2u64(unsigned bits) {
    __half2 h = *reinterpret_cast<__half2*>(&bits);
    float2 f = __half22float2(h);
    unsigned long long r;
    asm("mov.b64 %0, {%1, %2};" : "=l"(r) : "f"(f.x), "f"(f.y));
    return r;
}
__device__ __forceinline__ float upk_sum(unsigned long long v) {
    float lo, hi;
    asm("mov.b64 {%0, %1}, %2;" : "=f"(lo), "=f"(hi) : "l"(v));
    return lo + hi;
}

// Convert one slot (2 rows x 256 fp32 -> fp16) into smem, lane layout
// matching the dot (f4 at lane and lane+32). Warp-local, no sync needed.
__device__ __forceinline__ void conv_slot(uint4* wq, int slot,
                                          const float4* src0, const float4* src1,
                                          int lane) {
    float4 a0 = src0[lane], a1 = src0[lane+32];
    float4 c0 = src1[lane], c1 = src1[lane+32];
    uint4 qa, qb;
    __half2 h;
    h = __floats2half2_rn(a0.x, a0.y); qa.x = *reinterpret_cast<unsigned*>(&h);
    h = __floats2half2_rn(a0.z, a0.w); qa.y = *reinterpret_cast<unsigned*>(&h);
    h = __floats2half2_rn(a1.x, a1.y); qa.z = *reinterpret_cast<unsigned*>(&h);
    h = __floats2half2_rn(a1.z, a1.w); qa.w = *reinterpret_cast<unsigned*>(&h);
    h = __floats2half2_rn(c0.x, c0.y); qb.x = *reinterpret_cast<unsigned*>(&h);
    h = __floats2half2_rn(c0.z, c0.w); qb.y = *reinterpret_cast<unsigned*>(&h);
    h = __floats2half2_rn(c1.x, c1.y); qb.z = *reinterpret_cast<unsigned*>(&h);
    h = __floats2half2_rn(c1.z, c1.w); qb.w = *reinterpret_cast<unsigned*>(&h);
    wq[slot*64 + lane]      = qa;
    wq[slot*64 + 32 + lane] = qb;
}

// ============================================================
// Persistent step kernel. Warp w = module i, rows h0=bid, h1=128+bid.
// ALL nonzero wm blocks + wrec live in SMEM as fp16 (converted at preload).
// Dots run on packed f32x2 FMA with fp32 accumulation.
// ============================================================
__global__ void __launch_bounds__(NTHR, 1)
step_kernel(const float* __restrict__ wm,
            const float* __restrict__ conn,
            const float* __restrict__ wrec,
            float* __restrict__ out) {
    extern __shared__ uint4 wq[];        // [SLOTCAP][2][32] uint4 = 200 KB
    __shared__ float hy_sh[NROW];        // 16 KB snapshot
    __shared__ int   list_sh[MM][MM];
    __shared__ int   cnt_sh[MM];
    __shared__ float scal_sh[MM];

    int tid  = threadIdx.x;
    int lane = tid & 31;
    int i    = tid >> 5;                 // warp = module
    int h0   = blockIdx.x;
    int h1   = 128 + blockIdx.x;

    if (tid < MM) {
        int c = 0; float s = 0.f;
#pragma unroll
        for (int o = 0; o < MM; ++o) {
            float v = conn[tid*MM + o];
            s += v;
            if (v != 0.f) list_sh[tid][c++] = o;
        }
        cnt_sh[tid]  = c;
        scal_sh[tid] = 1.f / fmaxf(s, 1.f);
    }
    __syncthreads();

    const int   cnt  = cnt_sh[i];
    const float scal = scal_sh[i];
    const float* wmb0 = wm + (((size_t)i*MM)*HH + h0)*HH;
    const float* wmb1 = wm + (((size_t)i*MM)*HH + h1)*HH;

    // deterministic slot allocation: slots 0..15 = wrec per module;
    // wm pool from slot 16, module order, capped at SLOTCAP.
    int myoff = MM, myKC = 0;
    {
        int off = MM;
        for (int m2 = 0; m2 < MM; ++m2) {
            int rem  = SLOTCAP - off;
            int take = cnt_sh[m2];
            if (take > rem) take = rem > 0 ? rem : 0;
            if (m2 == i) { myoff = off; myKC = take; }
            off += take;
        }
    }

    // ---- one-time fp16 convert+preload (warp-local writes) ----
    conv_slot(wq, i,
              (const float4*)(wrec + ((size_t)i*HH + h0)*HH),
              (const float4*)(wrec + ((size_t)i*HH + h1)*HH), lane);
    for (int k = 0; k < myKC; ++k) {
        int o = list_sh[i][k];
        conv_slot(wq, myoff + k,
                  (const float4*)(wmb0 + (size_t)o*HH*HH),
                  (const float4*)(wmb1 + (size_t)o*HH*HH), lane);
    }

    float hypA = 0.f, hzpA = 0.f, hypB = 0.f, hzpB = 0.f;
    float BvA = g_B[i*HH + h0];
    float BvB = g_B[i*HH + h1];

    float* state_out = out;                       // [T][M][2][H]
    float* fb_out    = out + (size_t)TT*MM*2*HH;  // [T][M][H]
    unsigned* barp = &g_bar;

    for (int t = 0; t < TT; ++t) {
        int p = t & 1;
        // cooperative snapshot of published hy (2 float4/thread)
        {
            const float4* src = (const float4*)g_hy[p];
            ((float4*)hy_sh)[tid]        = __ldcg(src + tid);
            ((float4*)hy_sh)[tid + NTHR] = __ldcg(src + tid + NTHR);
        }
        __syncthreads();

        const float4* hy4 = (const float4*)hy_sh;
        unsigned long long accA = 0ull, accB = 0ull;   // packed f32x2 accumulators
        unsigned long long accRA = 0ull, accRB = 0ull;

        // ---- cached fp16 blocks (normal path: all of them) ----
        for (int k = 0; k < myKC; ++k) {
            int o = list_sh[i][k];
            int sl = myoff + k;
            float4 b0 = hy4[o*64 + lane], b1 = hy4[o*64 + 32 + lane];
            unsigned long long hb0 = pk2(b0.x, b0.y), hb1 = pk2(b0.z, b0.w);
            unsigned long long hb2 = pk2(b1.x, b1.y), hb3 = pk2(b1.z, b1.w);
            uint4 qa = wq[sl*64 + lane];
            uint4 qb = wq[sl*64 + 32 + lane];
            fma2(accA, h2u64(qa.x), hb0); fma2(accA, h2u64(qa.y), hb1);
            fma2(accA, h2u64(qa.z), hb2); fma2(accA, h2u64(qa.w), hb3);
            fma2(accB, h2u64(qb.x), hb0); fma2(accB, h2u64(qb.y), hb1);
            fma2(accB, h2u64(qb.z), hb2); fma2(accB, h2u64(qb.w), hb3);
        }
        // ---- overflow blocks from L2, fp32 (statistically never runs) ----
        float fbxA = 0.f, fbxB = 0.f;
        for (int k = myKC; k < cnt; ++k) {
            int o = list_sh[i][k];
            const float4* w0 = (const float4*)(wmb0 + (size_t)o*HH*HH);
            const float4* w1 = (const float4*)(wmb1 + (size_t)o*HH*HH);
            float4 b0 = hy4[o*64 + lane], b1 = hy4[o*64 + 32 + lane];
            fbxA += dotf4(w0[lane], b0) + dotf4(w0[lane+32], b1);
            fbxB += dotf4(w1[lane], b0) + dotf4(w1[lane+32], b1);
        }
        // ---- wrec (slot i) ----
        {
            float4 b0 = hy4[i*64 + lane], b1 = hy4[i*64 + 32 + lane];
            unsigned long long hb0 = pk2(b0.x, b0.y), hb1 = pk2(b0.z, b0.w);
            unsigned long long hb2 = pk2(b1.x, b1.y), hb3 = pk2(b1.z, b1.w);
            uint4 qa = wq[i*64 + lane];
            uint4 qb = wq[i*64 + 32 + lane];
            fma2(accRA, h2u64(qa.x), hb0); fma2(accRA, h2u64(qa.y), hb1);
            fma2(accRA, h2u64(qa.z), hb2); fma2(accRA, h2u64(qa.w), hb3);
            fma2(accRB, h2u64(qb.x), hb0); fma2(accRB, h2u64(qb.y), hb1);
            fma2(accRB, h2u64(qb.z), hb2); fma2(accRB, h2u64(qb.w), hb3);
        }

        float fbA  = upk_sum(accA) + fbxA;
        float fbB  = upk_sum(accB) + fbxB;
        float recA = upk_sum(accRA);
        float recB = upk_sum(accRB);

#pragma unroll
        for (int off = 16; off; off >>= 1) {
            fbA  += __shfl_xor_sync(0xffffffffu, fbA,  off);
            fbB  += __shfl_xor_sync(0xffffffffu, fbB,  off);
            recA += __shfl_xor_sync(0xffffffffu, recA, off);
            recB += __shfl_xor_sync(0xffffffffu, recB, off);
        }
        fbA *= scal; fbB *= scal;
        float preA = fbA + recA + BvA;
        float preB = fbB + recB + BvB;
        float hznA = hzpA + DT_ * (tanhf(preA) - GAMMA_*hypA - EPS_*hzpA);
        float hynA = hypA + DT_ * hznA;
        float hznB = hzpB + DT_ * (tanhf(preB) - GAMMA_*hypB - EPS_*hzpB);
        float hynB = hypB + DT_ * hznB;
        hzpA = hznA; hypA = hynA; hzpB = hznB; hypB = hynB;

        size_t sb = ((size_t)(t*MM + i)*2)*HH;
        if (lane == 0) {
            state_out[sb + h0]      = hynA;
            state_out[sb + HH + h0] = hznA;
            fb_out[(size_t)(t*MM + i)*HH + h0] = fbA;
            __stcg(&g_hy[1-p][i*HH + h0], hynA);
        } else if (lane == 1) {
            state_out[sb + h1]      = hynB;
            state_out[sb + HH + h1] = hznB;
            fb_out[(size_t)(t*MM + i)*HH + h1] = fbB;
            __stcg(&g_hy[1-p][i*HH + h1], hynB);
        }

        if (t == TT-1) break;

        // prefetch next-step B while the barrier drains
        BvA = g_B[(size_t)(t+1)*NROW + i*HH + h0];
        BvB = g_B[(size_t)(t+1)*NROW + i*HH + h1];

        __syncthreads();                 // all rows of CTA published
        if (tid == 0) {
            asm volatile("red.release.gpu.global.add.u32 [%0], 1;"
                         :: "l"(barp) : "memory");
            unsigned target = (unsigned)NB * (unsigned)(t + 1);
            unsigned v;
            do {
                asm volatile("ld.acquire.gpu.global.u32 %0, [%1];"
                             : "=r"(v) : "l"(barp) : "memory");
            } while (v < target);
        }
        __syncthreads();
    }
}

extern "C" void kernel_launch(void* const* d_in, const int* in_sizes, int n_in,
                              void* d_out, int out_size) {
    const float* x     = (const float*)d_in[0];
    const float* wm    = (const float*)d_in[1];
    const float* conn  = (const float*)d_in[2];
    const float* mask  = (const float*)d_in[3];
    const float* W_in  = (const float*)d_in[4];
    const float* W_rec = (const float*)d_in[5];
    const float* bias  = (const float*)d_in[6];
    float* out = (float*)d_out;

    void *hy_ptr, *bar_ptr;
    cudaGetSymbolAddress(&hy_ptr,  g_hy);
    cudaGetSymbolAddress(&bar_ptr, g_bar);

    cudaMemsetAsync(hy_ptr, 0, sizeof(float)*NROW);
    cudaMemsetAsync(bar_ptr, 0, sizeof(unsigned));

    cudaFuncSetAttribute(step_kernel,
                         cudaFuncAttributeMaxDynamicSharedMemorySize, DSMEM_BYTES);

    bin_kernel<<<dim3(TT, MM), BIN_THR>>>(x, mask, W_in, bias);
    step_kernel<<<NB, NTHR, DSMEM_BYTES>>>(wm, conn, W_rec, out);
}

// round 14
// speedup vs baseline: 1.3650x; 1.0518x over previous
#include <cuda_runtime.h>
#include <cuda_fp16.h>

#define TT 256
#define MM 16
#define HH 256
#define II 128
#define NROW (MM*HH)          // 4096
#define NB 128                // 128 CTAs; 16 warps each; warp owns 2 rows of its module
#define NTHR 512
#define SLOTCAP 200           // fp16 weight slots; 1 slot = 2 rows x 256 half = 1KB
#define DSMEM_BYTES (SLOTCAP*1024)

#define DT_ 0.042f
#define GAMMA_ 2.7f
#define EPS_ 4.7f

// ---- persistent scratch (no cudaMalloc allowed) ----
__device__ float    g_B[TT*NROW];     // W_in@u + bias, 4 MB (computed in-kernel)
__device__ float    g_hy[2][NROW];    // double-buffered published hy
__device__ unsigned g_bar;

__device__ __forceinline__ float dotf4(float4 a, float4 b) {
    return a.x*b.x + a.y*b.y + a.z*b.z + a.w*b.w;
}

// ---- packed f32x2 helpers (FFMA2 path) ----
__device__ __forceinline__ unsigned long long pk2(float lo, float hi) {
    unsigned long long r;
    asm("mov.b64 %0, {%1, %2};" : "=l"(r) : "f"(lo), "f"(hi));
    return r;
}
__device__ __forceinline__ void fma2(unsigned long long& acc,
                                     unsigned long long a, unsigned long long b) {
    asm("fma.rn.f32x2 %0, %1, %2, %3;" : "=l"(acc) : "l"(a), "l"(b), "l"(acc));
}
__device__ __forceinline__ unsigned long long h2u64(unsigned bits) {
    __half2 h = *reinterpret_cast<__half2*>(&bits);
    float2 f = __half22float2(h);
    unsigned long long r;
    asm("mov.b64 %0, {%1, %2};" : "=l"(r) : "f"(f.x), "f"(f.y));
    return r;
}
__device__ __forceinline__ float upk_sum(unsigned long long v) {
    float lo, hi;
    asm("mov.b64 {%0, %1}, %2;" : "=f"(lo), "=f"(hi) : "l"(v));
    return lo + hi;
}

// Convert one slot (2 rows x 256 fp32 -> fp16) into smem; lane layout
// matches the dot (f4 at lane and lane+32). Warp-local.
__device__ __forceinline__ void conv_slot(uint4* wq, int slot,
                                          const float4* src0, const float4* src1,
                                          int lane) {
    float4 a0 = src0[lane], a1 = src0[lane+32];
    float4 c0 = src1[lane], c1 = src1[lane+32];
    uint4 qa, qb;
    __half2 h;
    h = __floats2half2_rn(a0.x, a0.y); qa.x = *reinterpret_cast<unsigned*>(&h);
    h = __floats2half2_rn(a0.z, a0.w); qa.y = *reinterpret_cast<unsigned*>(&h);
    h = __floats2half2_rn(a1.x, a1.y); qa.z = *reinterpret_cast<unsigned*>(&h);
    h = __floats2half2_rn(a1.z, a1.w); qa.w = *reinterpret_cast<unsigned*>(&h);
    h = __floats2half2_rn(c0.x, c0.y); qb.x = *reinterpret_cast<unsigned*>(&h);
    h = __floats2half2_rn(c0.z, c0.w); qb.y = *reinterpret_cast<unsigned*>(&h);
    h = __floats2half2_rn(c1.x, c1.y); qb.z = *reinterpret_cast<unsigned*>(&h);
    h = __floats2half2_rn(c1.z, c1.w); qb.w = *reinterpret_cast<unsigned*>(&h);
    wq[slot*64 + lane]      = qa;
    wq[slot*64 + 32 + lane] = qb;
}

// ============================================================
// Persistent step kernel. Warp w = module i, rows h0=bid, h1=128+bid.
// Preamble: (a) compute g_B for OWN rows (no sync needed — consumed
// only by this warp), (b) convert all nonzero wm blocks + wrec into
// SMEM fp16. Main loop: pipelined fp16/FFMA2 dots + grid barrier.
// ============================================================
__global__ void __launch_bounds__(NTHR, 1)
step_kernel(const float* __restrict__ x,
            const float* __restrict__ wm,
            const float* __restrict__ conn,
            const float* __restrict__ input_mask,
            const float* __restrict__ W_in,
            const float* __restrict__ wrec,
            const float* __restrict__ bias,
            float* __restrict__ out) {
    extern __shared__ uint4 wq[];        // [SLOTCAP][2][32] uint4 = 200 KB
    __shared__ float hy_sh[NROW];        // 16 KB snapshot
    __shared__ int   list_sh[MM][MM];
    __shared__ int   cnt_sh[MM];
    __shared__ float scal_sh[MM];

    int tid  = threadIdx.x;
    int lane = tid & 31;
    int i    = tid >> 5;                 // warp = module
    int h0   = blockIdx.x;
    int h1   = 128 + blockIdx.x;
    int row0 = i*HH + h0;
    int row1 = i*HH + h1;

    if (tid < MM) {
        int c = 0; float s = 0.f;
#pragma unroll
        for (int o = 0; o < MM; ++o) {
            float v = conn[tid*MM + o];
            s += v;
            if (v != 0.f) list_sh[tid][c++] = o;
        }
        cnt_sh[tid]  = c;
        scal_sh[tid] = 1.f / fmaxf(s, 1.f);
    }
    __syncthreads();

    const int   cnt  = cnt_sh[i];
    const float scal = scal_sh[i];
    const float* wmb0 = wm + (((size_t)i*MM)*HH + h0)*HH;
    const float* wmb1 = wm + (((size_t)i*MM)*HH + h1)*HH;

    // ---- (a) compute g_B for own 2 rows, all 256 steps (warp-local) ----
    {
        float4 wA = ((const float4*)(W_in + ((size_t)i*HH + h0)*II))[lane];
        float4 wB = ((const float4*)(W_in + ((size_t)i*HH + h1)*II))[lane];
        float maskv = input_mask[i];
        float biasA = bias[i*HH + h0];
        float biasB = bias[i*HH + h1];
        for (int t = 0; t < TT; ++t) {
            float4 x4 = __ldg(((const float4*)(x + (size_t)t*II)) + lane);
            float pA = dotf4(wA, x4);
            float pB = dotf4(wB, x4);
#pragma unroll
            for (int off = 16; off; off >>= 1) {
                pA += __shfl_xor_sync(0xffffffffu, pA, off);
                pB += __shfl_xor_sync(0xffffffffu, pB, off);
            }
            if (lane == 0) {
                g_B[(size_t)t*NROW + row0] = maskv*pA + biasA;
                g_B[(size_t)t*NROW + row1] = maskv*pB + biasB;
            }
        }
    }

    // deterministic slot allocation: slots 0..15 = wrec per module;
    // wm pool from slot 16, module order, capped at SLOTCAP.
    int myoff = MM, myKC = 0;
    {
        int off = MM;
        for (int m2 = 0; m2 < MM; ++m2) {
            int rem  = SLOTCAP - off;
            int take = cnt_sh[m2];
            if (take > rem) take = rem > 0 ? rem : 0;
            if (m2 == i) { myoff = off; myKC = take; }
            off += take;
        }
    }

    // ---- (b) one-time fp16 convert+preload (warp-local writes) ----
    conv_slot(wq, i,
              (const float4*)(wrec + ((size_t)i*HH + h0)*HH),
              (const float4*)(wrec + ((size_t)i*HH + h1)*HH), lane);
    for (int k = 0; k < myKC; ++k) {
        int o = list_sh[i][k];
        conv_slot(wq, myoff + k,
                  (const float4*)(wmb0 + (size_t)o*HH*HH),
                  (const float4*)(wmb1 + (size_t)o*HH*HH), lane);
    }

    float hypA = 0.f, hzpA = 0.f, hypB = 0.f, hzpB = 0.f;
    float BvA = g_B[row0];   // own warp wrote these; no fence needed
    float BvB = g_B[row1];

    float* state_out = out;                       // [T][M][2][H]
    float* fb_out    = out + (size_t)TT*MM*2*HH;  // [T][M][H]
    unsigned* barp = &g_bar;

    for (int t = 0; t < TT; ++t) {
        int p = t & 1;
        // cooperative snapshot of published hy (2 float4/thread)
        {
            const float4* src = (const float4*)g_hy[p];
            ((float4*)hy_sh)[tid]        = __ldcg(src + tid);
            ((float4*)hy_sh)[tid + NTHR] = __ldcg(src + tid + NTHR);
        }
        __syncthreads();

        const float4* hy4 = (const float4*)hy_sh;
        unsigned long long accA = 0ull, accB = 0ull;
        unsigned long long accRA = 0ull, accRB = 0ull;

        // ---- pipelined fp16 blocks: 1-slot lookahead, branch-free ----
        uint4  qa_n, qb_n; float4 b0_n, b1_n;
        if (myKC > 0) {
            int o0 = list_sh[i][0];
            qa_n = wq[myoff*64 + lane];
            qb_n = wq[myoff*64 + 32 + lane];
            b0_n = hy4[o0*64 + lane];
            b1_n = hy4[o0*64 + 32 + lane];
        }
        for (int k = 0; k < myKC; ++k) {
            uint4  qa = qa_n, qb = qb_n;
            float4 b0 = b0_n, b1 = b1_n;
            int kn = (k+1 < myKC) ? k+1 : k;         // clamped prefetch
            int on = list_sh[i][kn];
            int sln = myoff + kn;
            qa_n = wq[sln*64 + lane];
            qb_n = wq[sln*64 + 32 + lane];
            b0_n = hy4[on*64 + lane];
            b1_n = hy4[on*64 + 32 + lane];

            unsigned long long hb0 = pk2(b0.x, b0.y), hb1 = pk2(b0.z, b0.w);
            unsigned long long hb2 = pk2(b1.x, b1.y), hb3 = pk2(b1.z, b1.w);
            fma2(accA, h2u64(qa.x), hb0); fma2(accA, h2u64(qa.y), hb1);
            fma2(accA, h2u64(qa.z), hb2); fma2(accA, h2u64(qa.w), hb3);
            fma2(accB, h2u64(qb.x), hb0); fma2(accB, h2u64(qb.y), hb1);
            fma2(accB, h2u64(qb.z), hb2); fma2(accB, h2u64(qb.w), hb3);
        }
        // ---- overflow blocks from L2, fp32 (statistically never runs) ----
        float fbxA = 0.f, fbxB = 0.f;
        for (int k = myKC; k < cnt; ++k) {
            int o = list_sh[i][k];
            const float4* w0 = (const float4*)(wmb0 + (size_t)o*HH*HH);
            const float4* w1 = (const float4*)(wmb1 + (size_t)o*HH*HH);
            float4 b0 = hy4[o*64 + lane], b1 = hy4[o*64 + 32 + lane];
            fbxA += dotf4(w0[lane], b0) + dotf4(w0[lane+32], b1);
            fbxB += dotf4(w1[lane], b0) + dotf4(w1[lane+32], b1);
        }
        // ---- wrec (slot i) ----
        {
            float4 b0 = hy4[i*64 + lane], b1 = hy4[i*64 + 32 + lane];
            unsigned long long hb0 = pk2(b0.x, b0.y), hb1 = pk2(b0.z, b0.w);
            unsigned long long hb2 = pk2(b1.x, b1.y), hb3 = pk2(b1.z, b1.w);
            uint4 qa = wq[i*64 + lane];
            uint4 qb = wq[i*64 + 32 + lane];
            fma2(accRA, h2u64(qa.x), hb0); fma2(accRA, h2u64(qa.y), hb1);
            fma2(accRA, h2u64(qa.z), hb2); fma2(accRA, h2u64(qa.w), hb3);
            fma2(accRB, h2u64(qb.x), hb0); fma2(accRB, h2u64(qb.y), hb1);
            fma2(accRB, h2u64(qb.z), hb2); fma2(accRB, h2u64(qb.w), hb3);
        }

        float fbA  = upk_sum(accA) + fbxA;
        float fbB  = upk_sum(accB) + fbxB;
        float recA = upk_sum(accRA);
        float recB = upk_sum(accRB);

#pragma unroll
        for (int off = 16; off; off >>= 1) {
            fbA  += __shfl_xor_sync(0xffffffffu, fbA,  off);
            fbB  += __shfl_xor_sync(0xffffffffu, fbB,  off);
            recA += __shfl_xor_sync(0xffffffffu, recA, off);
            recB += __shfl_xor_sync(0xffffffffu, recB, off);
        }
        fbA *= scal; fbB *= scal;
        float preA = fbA + recA + BvA;
        float preB = fbB + recB + BvB;
        float hznA = hzpA + DT_ * (tanhf(preA) - GAMMA_*hypA - EPS_*hzpA);
        float hynA = hypA + DT_ * hznA;
        float hznB = hzpB + DT_ * (tanhf(preB) - GAMMA_*hypB - EPS_*hzpB);
        float hynB = hypB + DT_ * hznB;
        hzpA = hznA; hypA = hynA; hzpB = hznB; hypB = hynB;

        size_t sb = ((size_t)(t*MM + i)*2)*HH;
        if (lane == 0) {
            state_out[sb + h0]      = hynA;
            state_out[sb + HH + h0] = hznA;
            fb_out[(size_t)(t*MM + i)*HH + h0] = fbA;
            __stcg(&g_hy[1-p][row0], hynA);
        } else if (lane == 1) {
            state_out[sb + h1]      = hynB;
            state_out[sb + HH + h1] = hznB;
            fb_out[(size_t)(t*MM + i)*HH + h1] = fbB;
            __stcg(&g_hy[1-p][row1], hynB);
        }

        if (t == TT-1) break;

        // prefetch next-step B while the barrier drains
        BvA = g_B[(size_t)(t+1)*NROW + row0];
        BvB = g_B[(size_t)(t+1)*NROW + row1];

        __syncthreads();                 // all rows of CTA published
        if (tid == 0) {
            asm volatile("red.release.gpu.global.add.u32 [%0], 1;"
                         :: "l"(barp) : "memory");
            unsigned target = (unsigned)NB * (unsigned)(t + 1);
            unsigned v;
            do {
                asm volatile("ld.acquire.gpu.global.u32 %0, [%1];"
                             : "=r"(v) : "l"(barp) : "memory");
            } while (v < target);
        }
        __syncthreads();
    }
}

extern "C" void kernel_launch(void* const* d_in, const int* in_sizes, int n_in,
                              void* d_out, int out_size) {
    const float* x     = (const float*)d_in[0];
    const float* wm    = (const float*)d_in[1];
    const float* conn  = (const float*)d_in[2];
    const float* mask  = (const float*)d_in[3];
    const float* W_in  = (const float*)d_in[4];
    const float* W_rec = (const float*)d_in[5];
    const float* bias  = (const float*)d_in[6];
    float* out = (float*)d_out;

    void *hy_ptr, *bar_ptr;
    cudaGetSymbolAddress(&hy_ptr,  g_hy);
    cudaGetSymbolAddress(&bar_ptr, g_bar);

    cudaMemsetAsync(hy_ptr, 0, sizeof(float)*NROW);
    cudaMemsetAsync(bar_ptr, 0, sizeof(unsigned));

    cudaFuncSetAttribute(step_kernel,
                         cudaFuncAttributeMaxDynamicSharedMemorySize, DSMEM_BYTES);

    step_kernel<<<NB, NTHR, DSMEM_BYTES>>>(x, wm, conn, mask, W_in, W_rec, bias, out);
}